// round 4
// baseline (speedup 1.0000x reference)
#include <cuda_runtime.h>
#include <float.h>

#define V    23
#define Hdim 256
#define Lseq 1024
#define TPB  128   // 4 warps, one chain (batch element) per CTA

// ---- Blackwell packed fp32x2 FMA (PTX-only; doubles fp32 throughput) ----
__device__ __forceinline__ unsigned long long ffma2(unsigned long long a,
                                                    unsigned long long b,
                                                    unsigned long long c) {
    unsigned long long d;
    asm("fma.rn.f32x2 %0, %1, %2, %3;" : "=l"(d) : "l"(a), "l"(b), "l"(c));
    return d;
}
__device__ __forceinline__ unsigned long long pack2(float x, float y) {
    unsigned long long d;
    asm("mov.b64 %0, {%1, %2};" : "=l"(d) : "f"(x), "f"(y));
    return d;
}
__device__ __forceinline__ float2 unpack2(unsigned long long a) {
    float2 r;
    asm("mov.b64 {%0, %1}, %2;" : "=f"(r.x), "=f"(r.y) : "l"(a));
    return r;
}

// Monotonic float->uint key: preserves float ordering (for integer redux max)
__device__ __forceinline__ unsigned fkey(float f) {
    unsigned u = __float_as_uint(f);
    return (u & 0x80000000u) ? ~u : (u | 0x80000000u);
}

__global__ __launch_bounds__(TPB, 4)
void daf_kernel(const int* __restrict__ x_tokens,
                const float* __restrict__ W1,
                const float* __restrict__ b1,
                const float* __restrict__ W2,
                const float* __restrict__ b2,
                float* __restrict__ out)
{
    __shared__ float sW1[V * Hdim];     // 23552 B, row y contiguous
    __shared__ float sh[Hdim];          // relu activations
    __shared__ float snet[48];          // 46 logits (+2 pad)
    __shared__ float sb2[48];
    __shared__ int   stok[Lseq];        // this chain's input tokens
    __shared__ unsigned char smul[V * V]; // (inv(s)*m) % V lookup
    __shared__ int   sres[2];           // loc, scale argmax results

    const int tid  = threadIdx.x;
    const int b    = blockIdx.x;
    const int lane = tid & 31;
    const int warp = tid >> 5;

    // ---- one-time setup ----
    for (int i = tid; i < V * Hdim; i += TPB) sW1[i] = W1[i];
    {
        const int* tokrow = x_tokens + (size_t)b * Lseq;
        for (int i = tid; i < Lseq; i += TPB) stok[i] = tokrow[i];
    }
    for (int i = tid; i < 48; i += TPB) sb2[i] = (i < 2 * V) ? b2[i] : 0.0f;
    for (int i = tid; i < V * V; i += TPB) {
        int s = i / V, m = i % V;
        int inv = 0;
        if (s) {
            for (int k = 1; k < V; ++k) if ((s * k) % V == 1) inv = k;
        }
        smul[i] = (unsigned char)((inv * m) % V);
    }

    // W2 resident in registers, packed as f32x2 pairs.
    // warp w owns outputs o = w*12 .. w*12+11 (o<46 valid); lane l owns j = l+32m.
    unsigned long long w2p[6][8];
    #pragma unroll
    for (int p = 0; p < 6; ++p) {
        int o = warp * 12 + 2 * p;
        #pragma unroll
        for (int m = 0; m < 8; ++m) {
            int j = lane + 32 * m;
            if (o + 1 < 2 * V) {
                float2 t = *reinterpret_cast<const float2*>(W2 + j * (2 * V) + o);
                w2p[p][m] = pack2(t.x, t.y);
            } else {
                w2p[p][m] = 0ull;
            }
        }
    }

    // hpre = acc@W1 + b1, maintained incrementally. acc0 = 0 -> hpre = b1.
    float hpre1 = b1[tid];
    float hpre2 = b1[tid + 128];

    float* op = out + (size_t)b * Lseq * V + tid;

    __syncthreads();

    for (int t = 0; t < Lseq; ++t) {
        // 1) activations to smem
        sh[tid]       = fmaxf(hpre1, 0.0f);
        sh[tid + 128] = fmaxf(hpre2, 0.0f);
        __syncthreads();

        // 2) matvec: 12 outputs per warp, f32x2-packed, W2 in registers
        unsigned long long a0p = 0, a1p = 0, a2p = 0, a3p = 0, a4p = 0, a5p = 0;
        const float* shl = sh + lane;
        #pragma unroll
        for (int m = 0; m < 8; ++m) {
            float hv = shl[32 * m];
            unsigned long long hp = pack2(hv, hv);
            a0p = ffma2(hp, w2p[0][m], a0p);
            a1p = ffma2(hp, w2p[1][m], a1p);
            a2p = ffma2(hp, w2p[2][m], a2p);
            a3p = ffma2(hp, w2p[3][m], a3p);
            a4p = ffma2(hp, w2p[4][m], a4p);
            a5p = ffma2(hp, w2p[5][m], a5p);
        }
        float2 q0 = unpack2(a0p), q1 = unpack2(a1p), q2 = unpack2(a2p);
        float2 q3 = unpack2(a3p), q4 = unpack2(a4p), q5 = unpack2(a5p);
        float r0 = q0.x, r1 = q0.y, r2  = q1.x, r3  = q1.y, r4  = q2.x, r5  = q2.y;
        float r6 = q3.x, r7 = q3.y, r8  = q4.x, r9  = q4.y, r10 = q5.x, r11 = q5.y;
        #pragma unroll
        for (int off = 16; off; off >>= 1) {
            r0  += __shfl_xor_sync(0xffffffffu, r0,  off);
            r1  += __shfl_xor_sync(0xffffffffu, r1,  off);
            r2  += __shfl_xor_sync(0xffffffffu, r2,  off);
            r3  += __shfl_xor_sync(0xffffffffu, r3,  off);
            r4  += __shfl_xor_sync(0xffffffffu, r4,  off);
            r5  += __shfl_xor_sync(0xffffffffu, r5,  off);
            r6  += __shfl_xor_sync(0xffffffffu, r6,  off);
            r7  += __shfl_xor_sync(0xffffffffu, r7,  off);
            r8  += __shfl_xor_sync(0xffffffffu, r8,  off);
            r9  += __shfl_xor_sync(0xffffffffu, r9,  off);
            r10 += __shfl_xor_sync(0xffffffffu, r10, off);
            r11 += __shfl_xor_sync(0xffffffffu, r11, off);
        }
        if (lane == 0) {
            int o = warp * 12;
            snet[o + 0]  = r0  + sb2[o + 0];
            snet[o + 1]  = r1  + sb2[o + 1];
            snet[o + 2]  = r2  + sb2[o + 2];
            snet[o + 3]  = r3  + sb2[o + 3];
            snet[o + 4]  = r4  + sb2[o + 4];
            snet[o + 5]  = r5  + sb2[o + 5];
            snet[o + 6]  = r6  + sb2[o + 6];
            snet[o + 7]  = r7  + sb2[o + 7];
            snet[o + 8]  = r8  + sb2[o + 8];
            snet[o + 9]  = r9  + sb2[o + 9];
            snet[o + 10] = r10 + sb2[o + 10];
            snet[o + 11] = r11 + sb2[o + 11];
        }
        __syncthreads();

        // 3) argmax over net[0:23] (warp 0 -> loc) and net[23:46] (warp 1 -> scale)
        //    first-index tie-break matches jnp.argmax
        if (warp < 2) {
            float v = (lane < V) ? snet[warp * V + lane] : -FLT_MAX;
            unsigned k = fkey(v);
            unsigned mk = __reduce_max_sync(0xffffffffu, k);
            unsigned ball = __ballot_sync(0xffffffffu, k == mk);
            if (lane == 0) sres[warp] = __ffs(ball) - 1;
        }
        __syncthreads();

        // 4) token arithmetic (redundant on all threads, avoids an extra sync)
        int loc = sres[0];
        int sc  = sres[1];
        int a0  = stok[t];
        int md  = a0 - loc;
        md += (md >> 31) & V;                 // (a0 - loc) mod 23
        int y = smul[sc * V + md];            // (inv(sc) * md) mod 23

        // 5) one-hot output row (covers the whole poisoned buffer over t)
        if (tid < V) *op = (tid == y) ? 1.0f : 0.0f;
        op += V;

        // 6) incremental state update: hpre += W1[y, :]
        hpre1 += sW1[y * Hdim + tid];
        hpre2 += sW1[y * Hdim + 128 + tid];
    }
}

extern "C" void kernel_launch(void* const* d_in, const int* in_sizes, int n_in,
                              void* d_out, int out_size) {
    const int*   x  = (const int*)d_in[0];
    const float* W1 = (const float*)d_in[1];
    const float* b1 = (const float*)d_in[2];
    const float* W2 = (const float*)d_in[3];
    const float* b2 = (const float*)d_in[4];
    int Bn = in_sizes[0] / Lseq;   // 512
    daf_kernel<<<Bn, TPB>>>(x, W1, b1, W2, b2, (float*)d_out);
}

// round 8
// speedup vs baseline: 2.0207x; 2.0207x over previous
#include <cuda_runtime.h>
#include <float.h>

#define V    23
#define Hdim 256
#define Lseq 1024
#define TPB  128   // 4 warps, one chain (batch element) per CTA

// ---- Blackwell packed fp32x2 FMA (PTX-only; doubles fp32 throughput) ----
__device__ __forceinline__ unsigned long long ffma2(unsigned long long a,
                                                    unsigned long long b,
                                                    unsigned long long c) {
    unsigned long long d;
    asm("fma.rn.f32x2 %0, %1, %2, %3;" : "=l"(d) : "l"(a), "l"(b), "l"(c));
    return d;
}
__device__ __forceinline__ unsigned long long pack2(float x, float y) {
    unsigned long long d;
    asm("mov.b64 %0, {%1, %2};" : "=l"(d) : "f"(x), "f"(y));
    return d;
}
__device__ __forceinline__ float2 unpack2(unsigned long long a) {
    float2 r;
    asm("mov.b64 {%0, %1}, %2;" : "=f"(r.x), "=f"(r.y) : "l"(a));
    return r;
}

// Monotonic float->uint key: preserves float ordering (for integer redux max)
__device__ __forceinline__ unsigned fkey(float f) {
    unsigned u = __float_as_uint(f);
    return (u & 0x80000000u) ? ~u : (u | 0x80000000u);
}

// Merge-reduce: fold value `hi` into `lo`, splitting ownership by lane bit.
// After MRG, lo on lanes with (lane&bit)==0 represents lo's output,
// on lanes with (lane&bit)!=0 represents hi's output; the lane-pair dimension
// `bit` has been summed.
#define MRG(lo, hi, bit) do {                                   \
    float _keep = (lane & (bit)) ? (hi) : (lo);                 \
    float _send = (lane & (bit)) ? (lo) : (hi);                 \
    (lo) = _keep + __shfl_xor_sync(0xffffffffu, _send, (bit));  \
} while (0)

__global__ __launch_bounds__(TPB, 4)
void daf_kernel(const int* __restrict__ x_tokens,
                const float* __restrict__ W1,
                const float* __restrict__ b1,
                const float* __restrict__ W2,
                const float* __restrict__ b2,
                float* __restrict__ out)
{
    __shared__ __align__(16) float sW1[V * Hdim]; // 23552 B, row y contiguous
    __shared__ float snet[2][48];                 // double-buffered logits
    __shared__ int   stok[Lseq];                  // this chain's input tokens
    __shared__ unsigned char smul[V * V];         // (inv(s)*m) % V lookup

    const int tid  = threadIdx.x;
    const int b    = blockIdx.x;
    const int lane = tid & 31;
    const int warp = tid >> 5;

    // ---- one-time setup ----
    for (int i = tid; i < V * Hdim; i += TPB) sW1[i] = W1[i];
    {
        const int* tokrow = x_tokens + (size_t)b * Lseq;
        for (int i = tid; i < Lseq; i += TPB) stok[i] = tokrow[i];
    }
    for (int i = tid; i < V * V; i += TPB) {
        int s = i / V, m = i % V;
        int inv = 0;
        if (s) {
            for (int k = 1; k < V; ++k) if ((s * k) % V == 1) inv = k;
        }
        smul[i] = (unsigned char)((inv * m) % V);
    }

    // Per-lane h-row ownership: j_m = (m<4) ? 4*lane+m : 128 + 4*lane + (m-4)
    // (enables float4 loads from sW1 and b1-free pack layout)
    int jidx[8];
    #pragma unroll
    for (int m = 0; m < 8; ++m)
        jidx[m] = (m < 4) ? (4 * lane + m) : (124 + 4 * lane + m);

    // W2 resident in registers, packed as f32x2 pairs.
    // warp w owns outputs o = w*12 .. w*12+11 (o<46 valid).
    unsigned long long w2p[6][8];
    #pragma unroll
    for (int p = 0; p < 6; ++p) {
        int o = warp * 12 + 2 * p;
        #pragma unroll
        for (int m = 0; m < 8; ++m) {
            if (o + 1 < 2 * V) {
                float2 t = *reinterpret_cast<const float2*>(W2 + jidx[m] * (2 * V) + o);
                w2p[p][m] = pack2(t.x, t.y);
            } else {
                w2p[p][m] = 0ull;
            }
        }
    }

    // bias in lane registers (added at argmax-read time)
    float rb2a = (lane < V) ? b2[lane]     : 0.0f;
    float rb2b = (lane < V) ? b2[V + lane] : 0.0f;

    // hpre replicated per warp, in registers. acc0 = 0 -> hpre = b1.
    float hp8[8];
    #pragma unroll
    for (int m = 0; m < 8; ++m) hp8[m] = b1[jidx[m]];

    // final-lane -> local output index mapping for the merge reduction
    const int b1b = (lane >> 1) & 1, b2b = (lane >> 2) & 1;
    const int b3b = (lane >> 3) & 1, b4b = (lane >> 4) & 1;
    const int o_loc = warp * 12 + (b1b ? (2 + 3 * b3b + 6 * b4b)
                                       : (b2b + 3 * b3b + 6 * b4b));

    float* op = out + (size_t)b * Lseq * V;

    __syncthreads();

    for (int t = 0; t < Lseq; ++t) {
        // 1) matvec: each warp has ALL of h in registers (relu on the fly)
        unsigned long long a0 = 0, a1 = 0, a2 = 0, a3 = 0, a4 = 0, a5 = 0;
        #pragma unroll
        for (int m = 0; m < 8; ++m) {
            float hv = fmaxf(hp8[m], 0.0f);
            unsigned long long hp = pack2(hv, hv);
            a0 = ffma2(hp, w2p[0][m], a0);
            a1 = ffma2(hp, w2p[1][m], a1);
            a2 = ffma2(hp, w2p[2][m], a2);
            a3 = ffma2(hp, w2p[3][m], a3);
            a4 = ffma2(hp, w2p[4][m], a4);
            a5 = ffma2(hp, w2p[5][m], a5);
        }
        float2 q0 = unpack2(a0), q1 = unpack2(a1), q2 = unpack2(a2);
        float2 q3 = unpack2(a3), q4 = unpack2(a4), q5 = unpack2(a5);
        float r0 = q0.x, r1 = q0.y, r2  = q1.x, r3  = q1.y, r4  = q2.x, r5  = q2.y;
        float r6 = q3.x, r7 = q3.y, r8  = q4.x, r9  = q4.y, r10 = q5.x, r11 = q5.y;

        // 2) merge-tree reduction: 12 sums in 5 rounds, 13 shuffles total
        MRG(r0, r6, 16); MRG(r1, r7, 16); MRG(r2, r8, 16);
        MRG(r3, r9, 16); MRG(r4, r10, 16); MRG(r5, r11, 16);
        MRG(r0, r3, 8);  MRG(r1, r4, 8);  MRG(r2, r5, 8);
        MRG(r0, r1, 4);  r2 += __shfl_xor_sync(0xffffffffu, r2, 4);
        MRG(r0, r2, 2);
        r0 += __shfl_xor_sync(0xffffffffu, r0, 1);

        float* sn = snet[t & 1];
        sn[o_loc] = r0;            // duplicate lanes write identical values
        __syncthreads();           // the ONLY barrier per step

        // 3) both argmaxes, redundantly in every warp (first-index tie-break)
        float v1 = (lane < V) ? sn[lane]     + rb2a : -FLT_MAX;
        float v2 = (lane < V) ? sn[V + lane] + rb2b : -FLT_MAX;
        unsigned k1 = fkey(v1);
        unsigned m1 = __reduce_max_sync(0xffffffffu, k1);
        int loc = __ffs(__ballot_sync(0xffffffffu, k1 == m1)) - 1;
        unsigned k2 = fkey(v2);
        unsigned m2 = __reduce_max_sync(0xffffffffu, k2);
        int sc  = __ffs(__ballot_sync(0xffffffffu, k2 == m2)) - 1;

        // 4) token arithmetic (uniform across CTA)
        int a0t = stok[t];
        int md  = a0t - loc;
        md += (md >> 31) & V;                  // (a0 - loc) mod 23
        int y = smul[sc * V + md];             // (inv(sc) * md) mod 23

        // 5) one-hot output row (warp 3 only; covers whole poisoned buffer)
        if (warp == 3 && lane < V) op[lane] = (lane == y) ? 1.0f : 0.0f;
        op += V;

        // 6) per-warp state update: hpre += W1[y, :]
        const float4 wa = *reinterpret_cast<const float4*>(&sW1[y * Hdim + 4 * lane]);
        const float4 wb = *reinterpret_cast<const float4*>(&sW1[y * Hdim + 128 + 4 * lane]);
        hp8[0] += wa.x; hp8[1] += wa.y; hp8[2] += wa.z; hp8[3] += wa.w;
        hp8[4] += wb.x; hp8[5] += wb.y; hp8[6] += wb.z; hp8[7] += wb.w;
    }
}

extern "C" void kernel_launch(void* const* d_in, const int* in_sizes, int n_in,
                              void* d_out, int out_size) {
    const int*   x  = (const int*)d_in[0];
    const float* W1 = (const float*)d_in[1];
    const float* b1 = (const float*)d_in[2];
    const float* W2 = (const float*)d_in[3];
    const float* b2 = (const float*)d_in[4];
    int Bn = in_sizes[0] / Lseq;   // 512
    daf_kernel<<<Bn, TPB>>>(x, W1, b1, W2, b2, (float*)d_out);
}